// round 16
// baseline (speedup 1.0000x reference)
#include <cuda_runtime.h>
#include <cuda_bf16.h>
#include <math.h>
#include <stdint.h>

// ---------------- problem constants ----------------
#define BB    256
#define NTOT  175
#define NPAD  192
#define NWAY  20
#define NWPAD 64
#define KSHOT 5
#define QN    75
#define DD    512
#define LL    4
#define KNEI  5
#define TAUINV 10.0f
#define NKQ   (NWAY*KSHOT)

// ---------------- device scratch ----------------
__device__ float g_V   [(size_t)BB*NTOT*DD];
__device__ float g_V0  [(size_t)BB*NTOT*DD];
__device__ __nv_bfloat16 g_Vh[(size_t)BB*NPAD*DD];
__device__ __nv_bfloat16 g_Vl[(size_t)BB*NPAD*DD];
__device__ __nv_bfloat16 g_Mh[(size_t)BB*NTOT*DD];
__device__ __nv_bfloat16 g_Ml[(size_t)BB*NTOT*DD];
__device__ float g_gemm[(size_t)BB*NTOT*DD];
__device__ float g_P    [(size_t)BB*NWAY*DD];
__device__ float g_P0   [(size_t)BB*NWAY*DD];
__device__ __nv_bfloat16 g_PMh[(size_t)BB*NWAY*DD];
__device__ __nv_bfloat16 g_PMl[(size_t)BB*NWAY*DD];
__device__ float g_Pgemm[(size_t)BB*NWAY*DD];
__device__ float g_Pa   [(size_t)BB*NWAY*DD];
__device__ __nv_bfloat16 g_Pah[(size_t)BB*NWPAD*DD];
__device__ __nv_bfloat16 g_Pal[(size_t)BB*NWPAD*DD];
__device__ float g_sim [(size_t)BB*NTOT*NTOT];
__device__ float g_simQ[(size_t)BB*NPAD*NWPAD];
__device__ float g_G   [(size_t)BB*NWAY*NWAY];
__device__ __nv_bfloat16 g_iWh[(size_t)LL*DD*DD];
__device__ __nv_bfloat16 g_iWl[(size_t)LL*DD*DD];
__device__ __nv_bfloat16 g_pWh[(size_t)LL*DD*DD];
__device__ __nv_bfloat16 g_pWl[(size_t)LL*DD*DD];
__device__ float g_lossP[BB*32];
__device__ int   g_accP [BB*32];

// ---------------- helpers ----------------
__device__ __forceinline__ float blockSum(float v, float* red) {
    int tid = threadIdx.x;
    #pragma unroll
    for (int off = 16; off; off >>= 1) v += __shfl_down_sync(0xffffffffu, v, off);
    if ((tid & 31) == 0) red[tid >> 5] = v;
    __syncthreads();
    float r = 0.f;
    int nw = blockDim.x >> 5;
    if (tid < 32) {
        if (tid < nw) r = red[tid];
        #pragma unroll
        for (int off = 16; off; off >>= 1) r += __shfl_down_sync(0xffffffffu, r, off);
        if (tid == 0) red[0] = r;
    }
    __syncthreads();
    r = red[0];
    __syncthreads();
    return r;
}

__device__ __forceinline__ float warpSum(float v) {
    #pragma unroll
    for (int off = 16; off; off >>= 1) v += __shfl_xor_sync(0xffffffffu, v, off);
    return v;
}

__device__ __forceinline__ uint32_t smem_u32(const void* p) {
    return (uint32_t)__cvta_generic_to_shared(p);
}

__device__ __forceinline__ void cpasync16(uint32_t dst, const void* src) {
    asm volatile("cp.async.ca.shared.global [%0], [%1], 16;" :: "r"(dst), "l"(src));
}
__device__ __forceinline__ void cpcommit() { asm volatile("cp.async.commit_group;"); }
__device__ __forceinline__ void cpwait0()  { asm volatile("cp.async.wait_group 0;"); }

__device__ __forceinline__ void ldsm4(uint32_t& r0, uint32_t& r1, uint32_t& r2, uint32_t& r3,
                                      uint32_t addr) {
    asm volatile("ldmatrix.sync.aligned.m8n8.x4.shared.b16 {%0,%1,%2,%3}, [%4];"
                 : "=r"(r0), "=r"(r1), "=r"(r2), "=r"(r3) : "r"(addr));
}

__device__ __forceinline__ void mma16(float* c, const uint32_t* a, const uint32_t* b) {
    asm volatile(
        "mma.sync.aligned.m16n8k16.row.col.f32.bf16.bf16.f32 "
        "{%0,%1,%2,%3}, {%4,%5,%6,%7}, {%8,%9}, {%0,%1,%2,%3};"
        : "+f"(c[0]), "+f"(c[1]), "+f"(c[2]), "+f"(c[3])
        : "r"(a[0]), "r"(a[1]), "r"(a[2]), "r"(a[3]), "r"(b[0]), "r"(b[1]));
}

__device__ __forceinline__ void split1(float x, __nv_bfloat16& h, __nv_bfloat16& l) {
    h = __float2bfloat16(x);
    l = __float2bfloat16(x - __bfloat162float(h));
}
__device__ __forceinline__ void split4(float4 v, uint2& hv, uint2& lv) {
    __nv_bfloat16 h0,h1,h2,h3,l0,l1,l2,l3;
    split1(v.x,h0,l0); split1(v.y,h1,l1); split1(v.z,h2,l2); split1(v.w,h3,l3);
    hv.x = (uint32_t)__bfloat16_as_ushort(h0) | ((uint32_t)__bfloat16_as_ushort(h1) << 16);
    hv.y = (uint32_t)__bfloat16_as_ushort(h2) | ((uint32_t)__bfloat16_as_ushort(h3) << 16);
    lv.x = (uint32_t)__bfloat16_as_ushort(l0) | ((uint32_t)__bfloat16_as_ushort(l1) << 16);
    lv.y = (uint32_t)__bfloat16_as_ushort(l2) | ((uint32_t)__bfloat16_as_ushort(l3) << 16);
}

// ---------------- setup kernels (4 prelaunches) ----------------

__global__ void k_zero() {
    int i = blockIdx.x * 256 + threadIdx.x;
    if (i < BB * 32) { g_lossP[i] = 0.f; g_accP[i] = 0; }
}

__global__ void k_prep(const float* __restrict__ iW, const float* __restrict__ pW) {
    const int WN = LL * DD * DD;
    int i = blockIdx.x * 256 + threadIdx.x;
    if (i < WN) {
        __nv_bfloat16 h, l; split1(iW[i], h, l); g_iWh[i] = h; g_iWl[i] = l;
        split1(pW[i], h, l); g_pWh[i] = h; g_pWl[i] = l;
    }
    const size_t padTotal = (size_t)BB * (NWPAD - NWAY) * DD;
    const size_t stride = (size_t)gridDim.x * 256;
    __nv_bfloat16 z = __float2bfloat16(0.f);
    for (size_t idx = i; idx < padTotal; idx += stride) {
        size_t bb = idx / ((NWPAD - NWAY) * DD);
        size_t rem = idx % ((NWPAD - NWAY) * DD);
        size_t r = NWAY + rem / DD, d = rem % DD;
        g_Pah[(bb * NWPAD + r) * DD + d] = z;
        g_Pal[(bb * NWPAD + r) * DD + d] = z;
    }
}

__global__ void k_initV(const float* __restrict__ in) {
    __shared__ float red[8];
    int r = blockIdx.x;
    int b = r / NPAD, n = r % NPAD;
    int t = threadIdx.x;  // 128
    size_t po = ((size_t)b * NPAD + n) * DD;
    if (n >= NTOT) {
        ((uint2*)(g_Vh + po))[t] = make_uint2(0, 0);
        ((uint2*)(g_Vl + po))[t] = make_uint2(0, 0);
        return;
    }
    size_t ro = ((size_t)b * NTOT + n) * DD;
    float4 v = ((const float4*)(in + ro))[t];
    float ss = v.x*v.x + v.y*v.y + v.z*v.z + v.w*v.w;
    ss = blockSum(ss, red);
    float inv = 1.f / fmaxf(sqrtf(ss), 1e-12f);
    float4 o = make_float4(v.x*inv, v.y*inv, v.z*inv, v.w*inv);
    ((float4*)(g_V  + ro))[t] = o;
    ((float4*)(g_V0 + ro))[t] = o;
    uint2 hv, lv; split4(o, hv, lv);
    ((uint2*)(g_Vh + po))[t] = hv;
    ((uint2*)(g_Vl + po))[t] = lv;
}

__global__ void k_initP(const float* __restrict__ in) {
    __shared__ float red[8];
    size_t row = blockIdx.x;
    int t = threadIdx.x;
    float4 v = ((const float4*)(in + row * DD))[t];
    float ss = v.x*v.x + v.y*v.y + v.z*v.z + v.w*v.w;
    ss = blockSum(ss, red);
    float inv = 1.f / fmaxf(sqrtf(ss), 1e-12f);
    float4 o = make_float4(v.x*inv, v.y*inv, v.z*inv, v.w*inv);
    ((float4*)(g_P  + row * DD))[t] = o;
    ((float4*)(g_P0 + row * DD))[t] = o;
}

// ============== bf16 hi/lo split tensor-core NT GEMM (64x64, cp.async) ==============
#define GSTG 20480
__global__ __launch_bounds__(128) void k_gemm_bf(
    const __nv_bfloat16* __restrict__ Ah, const __nv_bfloat16* __restrict__ Al,
    const __nv_bfloat16* __restrict__ Bh, const __nv_bfloat16* __restrict__ Bl,
    float* __restrict__ C, int M, int N, int ldc,
    size_t strA, size_t strB, size_t strC)
{
    __shared__ __align__(16) uint8_t smem[2 * GSTG];

    int tid = threadIdx.x;
    int m0 = blockIdx.y * 64, n0 = blockIdx.x * 64;
    const __nv_bfloat16* pAh = Ah + (size_t)blockIdx.z * strA + (size_t)m0 * DD;
    const __nv_bfloat16* pAl = Al + (size_t)blockIdx.z * strA + (size_t)m0 * DD;
    const __nv_bfloat16* pBh = Bh + (size_t)blockIdx.z * strB + (size_t)n0 * DD;
    const __nv_bfloat16* pBl = Bl + (size_t)blockIdx.z * strB + (size_t)n0 * DD;
    float* Cb = C + (size_t)blockIdx.z * strC;

    int warp = tid >> 5, lane = tid & 31;
    int warpM = warp >> 1, warpN = warp & 1;
    int j = lane >> 3, r8 = lane & 7;

    uint32_t offA[2], offB[2];
    #pragma unroll
    for (int mt = 0; mt < 2; mt++) {
        int row = warpM * 32 + mt * 16 + (j & 1) * 8 + r8;
        offA[mt] = (uint32_t)(row * 80 + (j >> 1) * 16);
    }
    #pragma unroll
    for (int nt2 = 0; nt2 < 2; nt2++) {
        int n = warpN * 32 + nt2 * 16 + (j >> 1) * 8 + r8;
        offB[nt2] = (uint32_t)(n * 80 + (j & 1) * 16);
    }
    uint32_t sbase = smem_u32(smem);

    float acc[2][4][4];
    #pragma unroll
    for (int mt = 0; mt < 2; mt++)
        #pragma unroll
        for (int nt = 0; nt < 4; nt++)
            #pragma unroll
            for (int r = 0; r < 4; r++) acc[mt][nt][r] = 0.f;

    int r0s = tid >> 2, c0s = tid & 3;
    int r1s = (tid + 128) >> 2, c1s = (tid + 128) & 3;

    auto issue = [&](int st, int kg) {
        uint32_t sb = sbase + st * GSTG;
        cpasync16(sb +          r0s*80 + c0s*16, pAh + (size_t)r0s*DD + kg + c0s*8);
        cpasync16(sb +          r1s*80 + c1s*16, pAh + (size_t)r1s*DD + kg + c1s*8);
        cpasync16(sb + 5120  +  r0s*80 + c0s*16, pAl + (size_t)r0s*DD + kg + c0s*8);
        cpasync16(sb + 5120  +  r1s*80 + c1s*16, pAl + (size_t)r1s*DD + kg + c1s*8);
        cpasync16(sb + 10240 +  r0s*80 + c0s*16, pBh + (size_t)r0s*DD + kg + c0s*8);
        cpasync16(sb + 10240 +  r1s*80 + c1s*16, pBh + (size_t)r1s*DD + kg + c1s*8);
        cpasync16(sb + 15360 +  r0s*80 + c0s*16, pBl + (size_t)r0s*DD + kg + c0s*8);
        cpasync16(sb + 15360 +  r1s*80 + c1s*16, pBl + (size_t)r1s*DD + kg + c1s*8);
        cpcommit();
    };

    issue(0, 0);
    int buf = 0;
    const int iters = DD / 32;
    for (int it = 0; it < iters; it++) {
        cpwait0();
        __syncthreads();
        if (it + 1 < iters) issue(buf ^ 1, (it + 1) * 32);
        uint32_t sb = sbase + buf * GSTG;
        #pragma unroll
        for (int s = 0; s < 2; s++) {
            uint32_t so = s * 32;
            uint32_t ah[2][4], al[2][4], bh[4][2], bl[4][2];
            #pragma unroll
            for (int mt = 0; mt < 2; mt++) {
                ldsm4(ah[mt][0], ah[mt][1], ah[mt][2], ah[mt][3], sb + offA[mt] + so);
                ldsm4(al[mt][0], al[mt][1], al[mt][2], al[mt][3], sb + 5120 + offA[mt] + so);
            }
            #pragma unroll
            for (int nt2 = 0; nt2 < 2; nt2++) {
                uint32_t q0,q1,q2,q3;
                ldsm4(q0,q1,q2,q3, sb + 10240 + offB[nt2] + so);
                bh[nt2*2][0]=q0; bh[nt2*2][1]=q1; bh[nt2*2+1][0]=q2; bh[nt2*2+1][1]=q3;
                ldsm4(q0,q1,q2,q3, sb + 15360 + offB[nt2] + so);
                bl[nt2*2][0]=q0; bl[nt2*2][1]=q1; bl[nt2*2+1][0]=q2; bl[nt2*2+1][1]=q3;
            }
            #pragma unroll
            for (int mt = 0; mt < 2; mt++)
                #pragma unroll
                for (int nt = 0; nt < 4; nt++) {
                    mma16(acc[mt][nt], ah[mt], bh[nt]);
                    mma16(acc[mt][nt], ah[mt], bl[nt]);
                    mma16(acc[mt][nt], al[mt], bh[nt]);
                }
        }
        buf ^= 1;
    }

    #pragma unroll
    for (int mt = 0; mt < 2; mt++) {
        #pragma unroll
        for (int nt = 0; nt < 4; nt++) {
            int row = m0 + warpM * 32 + mt * 16 + (lane >> 2);
            int col = n0 + warpN * 32 + nt * 8 + (lane & 3) * 2;
            if (row < M) {
                if (col < N)     Cb[(size_t)row * ldc + col]     = acc[mt][nt][0];
                if (col + 1 < N) Cb[(size_t)row * ldc + col + 1] = acc[mt][nt][1];
            }
            if (row + 8 < M) {
                if (col < N)     Cb[(size_t)(row + 8) * ldc + col]     = acc[mt][nt][2];
                if (col + 1 < N) Cb[(size_t)(row + 8) * ldc + col + 1] = acc[mt][nt][3];
            }
        }
    }
}

// ============== dual W-GEMM: 64x256 tile; y<700 instance, y>=700 proto ==============
// 256 threads, 8 warps (2x4), each warp 32x64. 100KB dynamic smem -> 2 CTAs/SM.
#define GW 51200   // per stage: Ah 5120 + Al 5120 + Bh 20480 + Bl 20480
#define YT_INST 700   // 44800/64
#define YT_PROT 80    // 5120/64
__global__ __launch_bounds__(256, 2) void k_gemm_w(
    const __nv_bfloat16* __restrict__ iAh, const __nv_bfloat16* __restrict__ iAl,
    const __nv_bfloat16* __restrict__ iBh, const __nv_bfloat16* __restrict__ iBl,
    float* __restrict__ iC,
    const __nv_bfloat16* __restrict__ qAh, const __nv_bfloat16* __restrict__ qAl,
    const __nv_bfloat16* __restrict__ qBh, const __nv_bfloat16* __restrict__ qBl,
    float* __restrict__ qC)
{
    extern __shared__ __align__(16) uint8_t dsm[];

    int tid = threadIdx.x;
    int yt = blockIdx.y;
    bool inst = yt < YT_INST;
    int m0 = (inst ? yt : (yt - YT_INST)) * 64;
    int n0 = blockIdx.x * 256;
    const __nv_bfloat16* pAh = (inst ? iAh : qAh) + (size_t)m0 * DD;
    const __nv_bfloat16* pAl = (inst ? iAl : qAl) + (size_t)m0 * DD;
    const __nv_bfloat16* pBh = (inst ? iBh : qBh) + (size_t)n0 * DD;
    const __nv_bfloat16* pBl = (inst ? iBl : qBl) + (size_t)n0 * DD;
    float* C = inst ? iC : qC;

    int warp = tid >> 5, lane = tid & 31;
    int warpM = warp >> 2, warpN = warp & 3;   // 2 x 4; warp tile 32 x 64
    int j = lane >> 3, r8 = lane & 7;

    uint32_t offA[2], offB[4];
    #pragma unroll
    for (int mt = 0; mt < 2; mt++) {
        int row = warpM * 32 + mt * 16 + (j & 1) * 8 + r8;
        offA[mt] = (uint32_t)(row * 80 + (j >> 1) * 16);
    }
    #pragma unroll
    for (int nt2 = 0; nt2 < 4; nt2++) {
        int n = warpN * 64 + nt2 * 16 + (j >> 1) * 8 + r8;
        offB[nt2] = (uint32_t)(n * 80 + (j & 1) * 16);
    }
    uint32_t sbase = smem_u32(dsm);

    float acc[2][8][4];
    #pragma unroll
    for (int mt = 0; mt < 2; mt++)
        #pragma unroll
        for (int nt = 0; nt < 8; nt++)
            #pragma unroll
            for (int r = 0; r < 4; r++) acc[mt][nt][r] = 0.f;

    // staging: A 256 chunks (1/thread); B 1024 chunks (4/thread) per array
    int rA = tid >> 2, cA = tid & 3;

    auto issue = [&](int st, int kg) {
        uint32_t sb = sbase + st * GW;
        cpasync16(sb +         rA*80 + cA*16, pAh + (size_t)rA*DD + kg + cA*8);
        cpasync16(sb + 5120 +  rA*80 + cA*16, pAl + (size_t)rA*DD + kg + cA*8);
        #pragma unroll
        for (int i = 0; i < 4; i++) {
            int c = tid + i * 256;
            int rB = c >> 2, cB = c & 3;
            cpasync16(sb + 10240 + rB*80 + cB*16, pBh + (size_t)rB*DD + kg + cB*8);
            cpasync16(sb + 30720 + rB*80 + cB*16, pBl + (size_t)rB*DD + kg + cB*8);
        }
        cpcommit();
    };

    issue(0, 0);
    int buf = 0;
    const int iters = DD / 32;
    for (int it = 0; it < iters; it++) {
        cpwait0();
        __syncthreads();
        if (it + 1 < iters) issue(buf ^ 1, (it + 1) * 32);
        uint32_t sb = sbase + buf * GW;
        #pragma unroll
        for (int s = 0; s < 2; s++) {
            uint32_t so = s * 32;
            uint32_t ah[2][4], al[2][4];
            #pragma unroll
            for (int mt = 0; mt < 2; mt++) {
                ldsm4(ah[mt][0], ah[mt][1], ah[mt][2], ah[mt][3], sb + offA[mt] + so);
                ldsm4(al[mt][0], al[mt][1], al[mt][2], al[mt][3], sb + 5120 + offA[mt] + so);
            }
            #pragma unroll
            for (int nt2 = 0; nt2 < 4; nt2++) {
                uint32_t bh[2][2], bl[2][2];
                uint32_t q0,q1,q2,q3;
                ldsm4(q0,q1,q2,q3, sb + 10240 + offB[nt2] + so);
                bh[0][0]=q0; bh[0][1]=q1; bh[1][0]=q2; bh[1][1]=q3;
                ldsm4(q0,q1,q2,q3, sb + 30720 + offB[nt2] + so);
                bl[0][0]=q0; bl[0][1]=q1; bl[1][0]=q2; bl[1][1]=q3;
                #pragma unroll
                for (int mt = 0; mt < 2; mt++)
                    #pragma unroll
                    for (int ntl = 0; ntl < 2; ntl++) {
                        int nt = nt2 * 2 + ntl;
                        mma16(acc[mt][nt], ah[mt], bh[ntl]);
                        mma16(acc[mt][nt], ah[mt], bl[ntl]);
                        mma16(acc[mt][nt], al[mt], bh[ntl]);
                    }
            }
        }
        buf ^= 1;
    }

    #pragma unroll
    for (int mt = 0; mt < 2; mt++) {
        #pragma unroll
        for (int nt = 0; nt < 8; nt++) {
            int row = m0 + warpM * 32 + mt * 16 + (lane >> 2);
            int col = n0 + warpN * 64 + nt * 8 + (lane & 3) * 2;
            C[(size_t)row * DD + col]           = acc[mt][nt][0];
            C[(size_t)row * DD + col + 1]       = acc[mt][nt][1];
            C[(size_t)(row + 8) * DD + col]     = acc[mt][nt][2];
            C[(size_t)(row + 8) * DD + col + 1] = acc[mt][nt][3];
        }
    }
}

// ============== symmetric sim GEMM: lower-triangle tiles + mirror write ==============
__constant__ int c_ty[6] = {0, 1, 1, 2, 2, 2};
__constant__ int c_tx[6] = {0, 0, 1, 0, 1, 2};
__global__ __launch_bounds__(128) void k_gemm_sym(
    const __nv_bfloat16* __restrict__ Vh, const __nv_bfloat16* __restrict__ Vl,
    float* __restrict__ C)
{
    __shared__ __align__(16) uint8_t smem[2 * GSTG];

    int tid = threadIdx.x;
    int ty = c_ty[blockIdx.x], tx = c_tx[blockIdx.x];
    int m0 = ty * 64, n0 = tx * 64;
    const __nv_bfloat16* pAh = Vh + (size_t)blockIdx.z * NPAD * DD + (size_t)m0 * DD;
    const __nv_bfloat16* pAl = Vl + (size_t)blockIdx.z * NPAD * DD + (size_t)m0 * DD;
    const __nv_bfloat16* pBh = Vh + (size_t)blockIdx.z * NPAD * DD + (size_t)n0 * DD;
    const __nv_bfloat16* pBl = Vl + (size_t)blockIdx.z * NPAD * DD + (size_t)n0 * DD;
    float* Cb = C + (size_t)blockIdx.z * NTOT * NTOT;

    int warp = tid >> 5, lane = tid & 31;
    int warpM = warp >> 1, warpN = warp & 1;
    int j = lane >> 3, r8 = lane & 7;

    uint32_t offA[2], offB[2];
    #pragma unroll
    for (int mt = 0; mt < 2; mt++) {
        int row = warpM * 32 + mt * 16 + (j & 1) * 8 + r8;
        offA[mt] = (uint32_t)(row * 80 + (j >> 1) * 16);
    }
    #pragma unroll
    for (int nt2 = 0; nt2 < 2; nt2++) {
        int n = warpN * 32 + nt2 * 16 + (j >> 1) * 8 + r8;
        offB[nt2] = (uint32_t)(n * 80 + (j & 1) * 16);
    }
    uint32_t sbase = smem_u32(smem);

    float acc[2][4][4];
    #pragma unroll
    for (int mt = 0; mt < 2; mt++)
        #pragma unroll
        for (int nt = 0; nt < 4; nt++)
            #pragma unroll
            for (int r = 0; r < 4; r++) acc[mt][nt][r] = 0.f;

    int r0s = tid >> 2, c0s = tid & 3;
    int r1s = (tid + 128) >> 2, c1s = (tid + 128) & 3;

    auto issue = [&](int st, int kg) {
        uint32_t sb = sbase + st * GSTG;
        cpasync16(sb +          r0s*80 + c0s*16, pAh + (size_t)r0s*DD + kg + c0s*8);
        cpasync16(sb +          r1s*80 + c1s*16, pAh + (size_t)r1s*DD + kg + c1s*8);
        cpasync16(sb + 5120  +  r0s*80 + c0s*16, pAl + (size_t)r0s*DD + kg + c0s*8);
        cpasync16(sb + 5120  +  r1s*80 + c1s*16, pAl + (size_t)r1s*DD + kg + c1s*8);
        cpasync16(sb + 10240 +  r0s*80 + c0s*16, pBh + (size_t)r0s*DD + kg + c0s*8);
        cpasync16(sb + 10240 +  r1s*80 + c1s*16, pBh + (size_t)r1s*DD + kg + c1s*8);
        cpasync16(sb + 15360 +  r0s*80 + c0s*16, pBl + (size_t)r0s*DD + kg + c0s*8);
        cpasync16(sb + 15360 +  r1s*80 + c1s*16, pBl + (size_t)r1s*DD + kg + c1s*8);
        cpcommit();
    };

    issue(0, 0);
    int buf = 0;
    const int iters = DD / 32;
    for (int it = 0; it < iters; it++) {
        cpwait0();
        __syncthreads();
        if (it + 1 < iters) issue(buf ^ 1, (it + 1) * 32);
        uint32_t sb = sbase + buf * GSTG;
        #pragma unroll
        for (int s = 0; s < 2; s++) {
            uint32_t so = s * 32;
            uint32_t ah[2][4], al[2][4], bh[4][2], bl[4][2];
            #pragma unroll
            for (int mt = 0; mt < 2; mt++) {
                ldsm4(ah[mt][0], ah[mt][1], ah[mt][2], ah[mt][3], sb + offA[mt] + so);
                ldsm4(al[mt][0], al[mt][1], al[mt][2], al[mt][3], sb + 5120 + offA[mt] + so);
            }
            #pragma unroll
            for (int nt2 = 0; nt2 < 2; nt2++) {
                uint32_t q0,q1,q2,q3;
                ldsm4(q0,q1,q2,q3, sb + 10240 + offB[nt2] + so);
                bh[nt2*2][0]=q0; bh[nt2*2][1]=q1; bh[nt2*2+1][0]=q2; bh[nt2*2+1][1]=q3;
                ldsm4(q0,q1,q2,q3, sb + 15360 + offB[nt2] + so);
                bl[nt2*2][0]=q0; bl[nt2*2][1]=q1; bl[nt2*2+1][0]=q2; bl[nt2*2+1][1]=q3;
            }
            #pragma unroll
            for (int mt = 0; mt < 2; mt++)
                #pragma unroll
                for (int nt = 0; nt < 4; nt++) {
                    mma16(acc[mt][nt], ah[mt], bh[nt]);
                    mma16(acc[mt][nt], ah[mt], bl[nt]);
                    mma16(acc[mt][nt], al[mt], bh[nt]);
                }
        }
        buf ^= 1;
    }

    #pragma unroll
    for (int mt = 0; mt < 2; mt++) {
        #pragma unroll
        for (int nt = 0; nt < 4; nt++) {
            int row = m0 + warpM * 32 + mt * 16 + (lane >> 2);
            int col = n0 + warpN * 32 + nt * 8 + (lane & 3) * 2;
            if (row < NTOT) {
                if (col < NTOT)     Cb[(size_t)row * NTOT + col]     = acc[mt][nt][0];
                if (col + 1 < NTOT) Cb[(size_t)row * NTOT + col + 1] = acc[mt][nt][1];
            }
            if (row + 8 < NTOT) {
                if (col < NTOT)     Cb[(size_t)(row + 8) * NTOT + col]     = acc[mt][nt][2];
                if (col + 1 < NTOT) Cb[(size_t)(row + 8) * NTOT + col + 1] = acc[mt][nt][3];
            }
        }
    }

    if (ty != tx) {
        __syncthreads();
        float* sT = (float*)smem;   // 64x65 floats
        #pragma unroll
        for (int mt = 0; mt < 2; mt++) {
            #pragma unroll
            for (int nt = 0; nt < 4; nt++) {
                int rl = warpM * 32 + mt * 16 + (lane >> 2);
                int cl = warpN * 32 + nt * 8 + (lane & 3) * 2;
                sT[(cl)     * 65 + rl]     = acc[mt][nt][0];
                sT[(cl + 1) * 65 + rl]     = acc[mt][nt][1];
                sT[(cl)     * 65 + rl + 8] = acc[mt][nt][2];
                sT[(cl + 1) * 65 + rl + 8] = acc[mt][nt][3];
            }
        }
        __syncthreads();
        for (int idx = tid; idx < 64 * 64; idx += 128) {
            int r = idx >> 6, c = idx & 63;
            int grow = n0 + r, gcol = m0 + c;
            if (grow < NTOT && gcol < NTOT)
                Cb[(size_t)grow * NTOT + gcol] = sT[r * 65 + c];
        }
    }
}

// ============== warp-per-row sparse step: top-5 + softmax + gather, no smem ==============
__global__ __launch_bounds__(256) void k_sparse(
    const float* __restrict__ sim, const float* __restrict__ V,
    __nv_bfloat16* __restrict__ mh, __nv_bfloat16* __restrict__ ml)
{
    int tid = threadIdx.x, w = tid >> 5, lane = tid & 31;
    int row = blockIdx.x * 8 + w;
    int b = row / NTOT;
    const float* sr = sim + (size_t)row * NTOT;
    float v[6];
    #pragma unroll
    for (int jj = 0; jj < 6; jj++) {
        int c = lane + jj * 32;
        v[jj] = (c < NTOT) ? sr[c] : -INFINITY;
    }
    float cv[KNEI]; int ci[KNEI];
    #pragma unroll
    for (int p = 0; p < KNEI; p++) {
        float bv = -INFINITY; int bc = 0x7fffffff;
        #pragma unroll
        for (int jj = 0; jj < 6; jj++)
            if (v[jj] > bv) { bv = v[jj]; bc = lane + jj * 32; }
        #pragma unroll
        for (int off = 16; off; off >>= 1) {
            float ov = __shfl_down_sync(0xffffffffu, bv, off);
            int   oc = __shfl_down_sync(0xffffffffu, bc, off);
            if (ov > bv || (ov == bv && oc < bc)) { bv = ov; bc = oc; }
        }
        bv = __shfl_sync(0xffffffffu, bv, 0);
        bc = __shfl_sync(0xffffffffu, bc, 0);
        cv[p] = bv; ci[p] = bc;
        if ((bc & 31) == lane) v[bc >> 5] = -INFINITY;
    }
    float wj[KNEI];
    {
        float mx = cv[0], s = 0.f;
        #pragma unroll
        for (int p = 0; p < KNEI; p++) { wj[p] = expf((cv[p] - mx) * TAUINV); s += wj[p]; }
        float inv = 1.f / s;
        #pragma unroll
        for (int p = 0; p < KNEI; p++) wj[p] *= inv;
    }
    const float* base = V + (size_t)b * NTOT * DD;
    const float4* nb[KNEI];
    #pragma unroll
    for (int p = 0; p < KNEI; p++) nb[p] = (const float4*)(base + (size_t)ci[p] * DD);
    float4 acc[4];
    #pragma unroll
    for (int i = 0; i < 4; i++) acc[i] = make_float4(0,0,0,0);
    #pragma unroll
    for (int p = 0; p < KNEI; p++) {
        #pragma unroll
        for (int i = 0; i < 4; i++) {
            float4 x = nb[p][lane + 32 * i];
            acc[i].x += wj[p]*x.x; acc[i].y += wj[p]*x.y;
            acc[i].z += wj[p]*x.z; acc[i].w += wj[p]*x.w;
        }
    }
    uint2* mhr = (uint2*)(mh + (size_t)row * DD);
    uint2* mlr = (uint2*)(ml + (size_t)row * DD);
    #pragma unroll
    for (int i = 0; i < 4; i++) {
        uint2 hv, lv; split4(acc[i], hv, lv);
        mhr[lane + 32 * i] = hv;
        mlr[lane + 32 * i] = lv;
    }
}

// fused prototype branch: sims + top-5 softmax + gather -> PMsg hi/lo
__global__ __launch_bounds__(256) void k_proto(const float* __restrict__ P,
                                               __nv_bfloat16* __restrict__ mh,
                                               __nv_bfloat16* __restrict__ ml)
{
    __shared__ float sP[NWAY * DD];
    __shared__ float sSim[NWAY][NWAY];
    __shared__ float sW[NWAY][KNEI];
    __shared__ int   sI[NWAY][KNEI];
    int b = blockIdx.x, tid = threadIdx.x;
    const float* Pb = P + (size_t)b * NWAY * DD;
    for (int i = tid; i < NWAY * DD; i += 256) sP[i] = Pb[i];
    __syncthreads();
    int warp = tid >> 5, lane = tid & 31;
    for (int p = warp; p < NWAY * NWAY; p += 8) {
        int r = p / NWAY, c = p % NWAY;
        float d = 0.f;
        for (int i = lane; i < DD; i += 32) d += sP[r * DD + i] * sP[c * DD + i];
        d = warpSum(d);
        if (lane == 0) sSim[r][c] = d;
    }
    __syncthreads();
    if (tid < NWAY) {
        float v[NWAY];
        #pragma unroll
        for (int c = 0; c < NWAY; c++) v[c] = sSim[tid][c];
        float cv[KNEI]; int ci[KNEI];
        #pragma unroll
        for (int p = 0; p < KNEI; p++) {
            float bv = -INFINITY; int bc = 0;
            #pragma unroll
            for (int c = 0; c < NWAY; c++)
                if (v[c] > bv) { bv = v[c]; bc = c; }
            cv[p] = bv; ci[p] = bc; v[bc] = -INFINITY;
        }
        float mx = cv[0], e[KNEI], s = 0.f;
        #pragma unroll
        for (int p = 0; p < KNEI; p++) { e[p] = expf((cv[p] - mx) * TAUINV); s += e[p]; }
        float inv = 1.f / s;
        #pragma unroll
        for (int p = 0; p < KNEI; p++) { sW[tid][p] = e[p] * inv; sI[tid][p] = ci[p]; }
    }
    __syncthreads();
    size_t base = (size_t)b * NWAY * DD;
    for (int e = tid; e < NWAY * DD; e += 256) {
        int r = e >> 9, d = e & (DD - 1);
        float a = 0.f;
        #pragma unroll
        for (int p = 0; p < KNEI; p++) a += sW[r][p] * sP[sI[r][p] * DD + d];
        __nv_bfloat16 hh, llv; split1(a, hh, llv);
        mh[base + e] = hh; ml[base + e] = llv;
    }
}

// block-per-row epilogue (R13 version — bandwidth-bound; proven best)
__global__ void k_epi(float* __restrict__ X, const float* __restrict__ X0,
                      const float* __restrict__ G, const float* __restrict__ bias,
                      const float* __restrict__ scaleArr, int layer,
                      __nv_bfloat16* __restrict__ oh, __nv_bfloat16* __restrict__ ol,
                      int rowsPerB, int padStride)
{
    __shared__ float red[8];
    int row = blockIdx.x;
    float s = scaleArr[layer];
    int t = threadIdx.x;  // 128
    float4 vv = ((const float4*)(X  + (size_t)row * DD))[t];
    float4 gg = ((const float4*)(G  + (size_t)row * DD))[t];
    float4 bb = ((const float4*)(bias))[t];
    float4 v0 = ((const float4*)(X0 + (size_t)row * DD))[t];
    float4 r4;
    r4.x = 0.8f*(vv.x + s*tanhf(gg.x + bb.x)) + 0.2f*v0.x;
    r4.y = 0.8f*(vv.y + s*tanhf(gg.y + bb.y)) + 0.2f*v0.y;
    r4.z = 0.8f*(vv.z + s*tanhf(gg.z + bb.z)) + 0.2f*v0.z;
    r4.w = 0.8f*(vv.w + s*tanhf(gg.w + bb.w)) + 0.2f*v0.w;
    float ss = r4.x*r4.x + r4.y*r4.y + r4.z*r4.z + r4.w*r4.w;
    ss = blockSum(ss, red);
    float inv = 1.f / fmaxf(sqrtf(ss), 1e-12f);
    r4.x*=inv; r4.y*=inv; r4.z*=inv; r4.w*=inv;
    ((float4*)(X + (size_t)row * DD))[t] = r4;
    if (oh) {
        int b = row / rowsPerB, n = row % rowsPerB;
        size_t po = ((size_t)b * padStride + n) * DD;
        uint2 hv, lv; split4(r4, hv, lv);
        ((uint2*)(oh + po))[t] = hv;
        ((uint2*)(ol + po))[t] = lv;
    }
}

// ============== fused VC + Pa + Gram (one block per batch) ==============
__global__ __launch_bounds__(256) void k_vcg(
    const float* __restrict__ V, const float* __restrict__ P,
    float* __restrict__ Pa, __nv_bfloat16* __restrict__ Pah,
    __nv_bfloat16* __restrict__ Pal, float* __restrict__ G,
    const float* __restrict__ alphaPtr)
{
    __shared__ float sPa[NWAY * DD];
    int b = blockIdx.x;
    int tid = threadIdx.x, w = tid >> 5, lane = tid & 31;
    float a = *alphaPtr;
    for (int c = w; c < NWAY; c += 8) {
        const float* base = V + ((size_t)b * NTOT + (size_t)c * KSHOT) * DD;
        float acc[16];
        #pragma unroll
        for (int i = 0; i < 16; i++) acc[i] = 0.f;
        #pragma unroll
        for (int k = 0; k < KSHOT; k++)
            #pragma unroll
            for (int i = 0; i < 16; i++)
                acc[i] += base[(size_t)k * DD + lane + 32 * i];
        float ss = 0.f;
        #pragma unroll
        for (int i = 0; i < 16; i++) { acc[i] *= 0.2f; ss += acc[i] * acc[i]; }
        ss = warpSum(ss);
        float inv = 1.f / fmaxf(sqrtf(ss), 1e-12f);
        const float* Prow = P + ((size_t)b * NWAY + c) * DD;
        float pa[16]; float ss2 = 0.f;
        #pragma unroll
        for (int i = 0; i < 16; i++) {
            pa[i] = a * Prow[lane + 32 * i] + (1.f - a) * acc[i] * inv;
            ss2 += pa[i] * pa[i];
        }
        ss2 = warpSum(ss2);
        float inv2 = 1.f / fmaxf(sqrtf(ss2), 1e-12f);
        float* PaRow = Pa + ((size_t)b * NWAY + c) * DD;
        __nv_bfloat16* hRow = Pah + ((size_t)b * NWPAD + c) * DD;
        __nv_bfloat16* lRow = Pal + ((size_t)b * NWPAD + c) * DD;
        #pragma unroll
        for (int i = 0; i < 16; i++) {
            float v = pa[i] * inv2;
            int d = lane + 32 * i;
            PaRow[d] = v;
            sPa[c * DD + d] = v;
            __nv_bfloat16 hh, ll; split1(v, hh, ll);
            hRow[d] = hh; lRow[d] = ll;
        }
    }
    __syncthreads();
    for (int p = w; p < NWAY * NWAY; p += 8) {
        int i = p / NWAY, jc = p % NWAY;
        float d = 0.f;
        for (int k = lane; k < DD; k += 32) d += sPa[i * DD + k] * sPa[jc * DD + k];
        d = warpSum(d);
        if (lane == 0) G[(size_t)b * NWAY * NWAY + p] = d;
    }
}

// warp-per-row guidance
__global__ __launch_bounds__(256) void k_guide2(
    float* __restrict__ V, __nv_bfloat16* __restrict__ Vh, __nv_bfloat16* __restrict__ Vl,
    const float* __restrict__ Pa, const float* __restrict__ G,
    const float* __restrict__ simsQ, const float* __restrict__ betaPtr,
    const int* __restrict__ qy, int layer, int writeV)
{
    __shared__ float sPa[NWAY * DD];
    __shared__ float sG[NWAY * NWAY];
    __shared__ float sSoft[8][NWAY];
    int b = blockIdx.x;
    int tid = threadIdx.x, w = tid >> 5, lane = tid & 31;
    float beta = *betaPtr;
    if (writeV) {
        const float* PaB = Pa + (size_t)b * NWAY * DD;
        for (int i = tid; i < NWAY * DD; i += 256) sPa[i] = PaB[i];
    }
    for (int i = tid; i < NWAY * NWAY; i += 256) sG[i] = G[(size_t)b * NWAY * NWAY + i];
    __syncthreads();
    int gw = blockIdx.y * 8 + w;
    float localLoss = 0.f; int localAcc = 0;
    for (int r = gw; r < NTOT; r += 32) {
        if (!writeV && r < NKQ) continue;
        float s = (lane < NWAY) ? simsQ[((size_t)b * NPAD + r) * NWPAD + lane] : -INFINITY;
        float mx = s;
        #pragma unroll
        for (int off = 16; off; off >>= 1) mx = fmaxf(mx, __shfl_xor_sync(0xffffffffu, mx, off));
        float e = (lane < NWAY) ? expf((s - mx) * TAUINV) : 0.f;
        float sum = warpSum(e);
        float soft = e / sum;
        if (lane < NWAY) sSoft[w][lane] = soft;
        __syncwarp();
        float tj = 0.f;
        if (lane < NWAY) {
            #pragma unroll
            for (int m = 0; m < NWAY; m++) tj += sSoft[w][m] * sG[m * NWAY + lane];
        }
        float ob = 1.f - beta;
        float contrib = (lane < NWAY) ? soft * (2.f * beta * ob * s + ob * ob * tj) : 0.f;
        float n2 = beta * beta + warpSum(contrib);
        float invn = 1.f / fmaxf(sqrtf(n2), 1e-12f);
        if (writeV) {
            float* Vrow = V + ((size_t)b * NTOT + r) * DD;
            __nv_bfloat16* VhRow = Vh + ((size_t)b * NPAD + r) * DD;
            __nv_bfloat16* VlRow = Vl + ((size_t)b * NPAD + r) * DD;
            #pragma unroll
            for (int i = 0; i < 16; i++) {
                int d = lane + 32 * i;
                float g = 0.f;
                #pragma unroll
                for (int m = 0; m < NWAY; m++) g += sSoft[w][m] * sPa[m * DD + d];
                float nv = (beta * Vrow[d] + ob * g) * invn;
                Vrow[d] = nv;
                __nv_bfloat16 hh, ll; split1(nv, hh, ll);
                VhRow[d] = hh; VlRow[d] = ll;
            }
        }
        if (r >= NKQ) {
            float logit = (lane < NWAY) ? 5.f * invn * (beta * s + ob * tj) : -INFINITY;
            float m2 = logit;
            #pragma unroll
            for (int off = 16; off; off >>= 1) m2 = fmaxf(m2, __shfl_xor_sync(0xffffffffu, m2, off));
            float ee = (lane < NWAY) ? expf(logit - m2) : 0.f;
            float ssum = warpSum(ee);
            float lse = m2 + logf(ssum);
            int lbl = qy[b * QN + (r - NKQ)];
            float ll = __shfl_sync(0xffffffffu, logit, lbl);
            if (lane == 0) localLoss += lse - ll;
            if (layer == LL - 1) {
                float bv = logit; int bi = lane;
                #pragma unroll
                for (int off = 16; off; off >>= 1) {
                    float ov = __shfl_xor_sync(0xffffffffu, bv, off);
                    int   oi = __shfl_xor_sync(0xffffffffu, bi, off);
                    if (ov > bv || (ov == bv && oi < bi)) { bv = ov; bi = oi; }
                }
                if (lane == 0) localAcc += (bi == lbl) ? 1 : 0;
            }
        }
    }
    if (lane == 0) {
        int pi = b * 32 + gw;
        g_lossP[pi] += localLoss;
        if (layer == LL - 1) g_accP[pi] = localAcc;
    }
}

__global__ void k_final(float* __restrict__ out) {
    __shared__ float red[8];
    int t = threadIdx.x;
    float ls = 0.f, ac = 0.f;
    for (int i = t; i < BB * 32; i += 256) { ls += g_lossP[i]; ac += (float)g_accP[i]; }
    float L = blockSum(ls, red);
    float A = blockSum(ac, red);
    if (t == 0) {
        out[0] = L / (float)(BB * QN * LL);
        out[1] = A / (float)(BB * QN);
    }
}

// ---------------- launch ----------------
extern "C" void kernel_launch(void* const* d_in, const int* in_sizes, int n_in,
                              void* d_out, int out_size)
{
    const float* V_feat = (const float*)d_in[0];
    const float* P_feat = (const float*)d_in[1];
    const int*   qy     = (const int*)  d_in[2];
    const float* igbW   = (const float*)d_in[3];
    const float* igbB   = (const float*)d_in[4];
    const float* igbS   = (const float*)d_in[5];
    const float* pgbW   = (const float*)d_in[6];
    const float* pgbB   = (const float*)d_in[7];
    const float* pgbS   = (const float*)d_in[8];
    const float* alpha  = (const float*)d_in[9];
    const float* beta   = (const float*)d_in[10];
    float* out = (float*)d_out;

    float *pV, *pV0, *pGemm, *pP, *pP0, *pPgemm, *pPa, *pSim, *pSimQ, *pG;
    __nv_bfloat16 *pVh, *pVl, *pMh, *pMl, *pPMh, *pPMl, *pPah, *pPal, *piWh, *piWl, *ppWh, *ppWl;
    cudaGetSymbolAddress((void**)&pV,    g_V);
    cudaGetSymbolAddress((void**)&pV0,   g_V0);
    cudaGetSymbolAddress((void**)&pVh,   g_Vh);
    cudaGetSymbolAddress((void**)&pVl,   g_Vl);
    cudaGetSymbolAddress((void**)&pMh,   g_Mh);
    cudaGetSymbolAddress((void**)&pMl,   g_Ml);
    cudaGetSymbolAddress((void**)&pGemm, g_gemm);
    cudaGetSymbolAddress((void**)&pP,    g_P);
    cudaGetSymbolAddress((void**)&pP0,   g_P0);
    cudaGetSymbolAddress((void**)&pPMh,  g_PMh);
    cudaGetSymbolAddress((void**)&pPMl,  g_PMl);
    cudaGetSymbolAddress((void**)&pPgemm,g_Pgemm);
    cudaGetSymbolAddress((void**)&pPa,   g_Pa);
    cudaGetSymbolAddress((void**)&pPah,  g_Pah);
    cudaGetSymbolAddress((void**)&pPal,  g_Pal);
    cudaGetSymbolAddress((void**)&pSim,  g_sim);
    cudaGetSymbolAddress((void**)&pSimQ, g_simQ);
    cudaGetSymbolAddress((void**)&pG,    g_G);
    cudaGetSymbolAddress((void**)&piWh,  g_iWh);
    cudaGetSymbolAddress((void**)&piWl,  g_iWl);
    cudaGetSymbolAddress((void**)&ppWh,  g_pWh);
    cudaGetSymbolAddress((void**)&ppWl,  g_pWl);

    cudaFuncSetAttribute(k_gemm_w, cudaFuncAttributeMaxDynamicSharedMemorySize, 2 * GW);

    k_zero<<<(BB * 32 + 255) / 256, 256>>>();
    k_prep<<<(LL * DD * DD + 255) / 256, 256>>>(igbW, pgbW);
    k_initV<<<BB * NPAD, 128>>>(V_feat);
    k_initP<<<BB * NWAY, 128>>>(P_feat);

    for (int i = 0; i < LL; i++) {
        // ---- graph step: sim + sparse + proto msg ----
        k_gemm_sym<<<dim3(6, 1, BB), 128>>>(pVh, pVl, pSim);
        k_sparse<<<(BB * NTOT) / 8, 256>>>(pSim, pV, pMh, pMl);
        k_proto<<<BB, 256>>>(pP, pPMh, pPMl);
        // ---- dual W-GEMM (64x256 tiles): instance + proto in one grid ----
        k_gemm_w<<<dim3(2, YT_INST + YT_PROT), 256, 2 * GW>>>(
            pMh, pMl, piWh + (size_t)i * DD * DD, piWl + (size_t)i * DD * DD, pGemm,
            pPMh, pPMl, ppWh + (size_t)i * DD * DD, ppWl + (size_t)i * DD * DD, pPgemm);
        // ---- epilogues ----
        k_epi<<<BB * NTOT, 128>>>(pV, pV0, pGemm, igbB + (size_t)i * DD, igbS, i,
                                  pVh, pVl, NTOT, NPAD);
        k_epi<<<BB * NWAY, 128>>>(pP, pP0, pPgemm, pgbB + (size_t)i * DD, pgbS, i,
                                  nullptr, nullptr, NWAY, NWAY);
        // ---- centers + adapted prototypes + Gram, simQ, guidance ----
        k_vcg<<<BB, 256>>>(pV, pP, pPa, pPah, pPal, pG, alpha);
        k_gemm_bf<<<dim3(1, 3, BB), 128>>>(pVh, pVl, pPah, pPal, pSimQ,
            NPAD, NWPAD, NWPAD, (size_t)NPAD * DD, (size_t)NWPAD * DD, (size_t)NPAD * NWPAD);
        int writeV = (i < LL - 1) ? 1 : 0;
        k_guide2<<<dim3(BB, 4), 256>>>(pV, pVh, pVl, pPa, pG, pSimQ, beta, qy, i, writeV);
    }
    k_final<<<1, 256>>>(out);
}

// round 17
// speedup vs baseline: 1.0649x; 1.0649x over previous
#include <cuda_runtime.h>
#include <cuda_bf16.h>
#include <math.h>
#include <stdint.h>

// ---------------- problem constants ----------------
#define BB    256
#define NTOT  175
#define NPAD  192
#define NWAY  20
#define NWPAD 64
#define KSHOT 5
#define QN    75
#define DD    512
#define LL    4
#define KNEI  5
#define TAUINV 10.0f
#define NKQ   (NWAY*KSHOT)

// ---------------- device scratch ----------------
__device__ float g_V   [(size_t)BB*NTOT*DD];
__device__ float g_V0  [(size_t)BB*NTOT*DD];
__device__ __nv_bfloat16 g_Vh[(size_t)BB*NPAD*DD];
__device__ __nv_bfloat16 g_Vl[(size_t)BB*NPAD*DD];
__device__ __nv_bfloat16 g_Mh[(size_t)BB*NTOT*DD];
__device__ __nv_bfloat16 g_Ml[(size_t)BB*NTOT*DD];
__device__ float g_gemm[(size_t)BB*NTOT*DD];
__device__ float g_P    [(size_t)BB*NWAY*DD];
__device__ float g_P0   [(size_t)BB*NWAY*DD];
__device__ __nv_bfloat16 g_PMh[(size_t)BB*NWAY*DD];
__device__ __nv_bfloat16 g_PMl[(size_t)BB*NWAY*DD];
__device__ float g_Pgemm[(size_t)BB*NWAY*DD];
__device__ float g_Pa   [(size_t)BB*NWAY*DD];
__device__ __nv_bfloat16 g_Pah[(size_t)BB*NWPAD*DD];
__device__ __nv_bfloat16 g_Pal[(size_t)BB*NWPAD*DD];
__device__ float g_sim [(size_t)BB*NTOT*NTOT];
__device__ float g_simQ[(size_t)BB*NPAD*NWPAD];
__device__ float g_G   [(size_t)BB*NWAY*NWAY];
__device__ __nv_bfloat16 g_iWh[(size_t)LL*DD*DD];
__device__ __nv_bfloat16 g_iWl[(size_t)LL*DD*DD];
__device__ __nv_bfloat16 g_pWh[(size_t)LL*DD*DD];
__device__ __nv_bfloat16 g_pWl[(size_t)LL*DD*DD];
__device__ float g_lossP[BB*32];
__device__ int   g_accP [BB*32];

// ---------------- helpers ----------------
__device__ __forceinline__ float blockSum(float v, float* red) {
    int tid = threadIdx.x;
    #pragma unroll
    for (int off = 16; off; off >>= 1) v += __shfl_down_sync(0xffffffffu, v, off);
    if ((tid & 31) == 0) red[tid >> 5] = v;
    __syncthreads();
    float r = 0.f;
    int nw = blockDim.x >> 5;
    if (tid < 32) {
        if (tid < nw) r = red[tid];
        #pragma unroll
        for (int off = 16; off; off >>= 1) r += __shfl_down_sync(0xffffffffu, r, off);
        if (tid == 0) red[0] = r;
    }
    __syncthreads();
    r = red[0];
    __syncthreads();
    return r;
}

__device__ __forceinline__ float warpSum(float v) {
    #pragma unroll
    for (int off = 16; off; off >>= 1) v += __shfl_xor_sync(0xffffffffu, v, off);
    return v;
}

__device__ __forceinline__ uint32_t smem_u32(const void* p) {
    return (uint32_t)__cvta_generic_to_shared(p);
}

__device__ __forceinline__ void cpasync16(uint32_t dst, const void* src) {
    asm volatile("cp.async.ca.shared.global [%0], [%1], 16;" :: "r"(dst), "l"(src));
}
__device__ __forceinline__ void cpcommit() { asm volatile("cp.async.commit_group;"); }
__device__ __forceinline__ void cpwait0()  { asm volatile("cp.async.wait_group 0;"); }

__device__ __forceinline__ void ldsm4(uint32_t& r0, uint32_t& r1, uint32_t& r2, uint32_t& r3,
                                      uint32_t addr) {
    asm volatile("ldmatrix.sync.aligned.m8n8.x4.shared.b16 {%0,%1,%2,%3}, [%4];"
                 : "=r"(r0), "=r"(r1), "=r"(r2), "=r"(r3) : "r"(addr));
}

__device__ __forceinline__ void mma16(float* c, const uint32_t* a, const uint32_t* b) {
    asm volatile(
        "mma.sync.aligned.m16n8k16.row.col.f32.bf16.bf16.f32 "
        "{%0,%1,%2,%3}, {%4,%5,%6,%7}, {%8,%9}, {%0,%1,%2,%3};"
        : "+f"(c[0]), "+f"(c[1]), "+f"(c[2]), "+f"(c[3])
        : "r"(a[0]), "r"(a[1]), "r"(a[2]), "r"(a[3]), "r"(b[0]), "r"(b[1]));
}

__device__ __forceinline__ void split1(float x, __nv_bfloat16& h, __nv_bfloat16& l) {
    h = __float2bfloat16(x);
    l = __float2bfloat16(x - __bfloat162float(h));
}
__device__ __forceinline__ void split4(float4 v, uint2& hv, uint2& lv) {
    __nv_bfloat16 h0,h1,h2,h3,l0,l1,l2,l3;
    split1(v.x,h0,l0); split1(v.y,h1,l1); split1(v.z,h2,l2); split1(v.w,h3,l3);
    hv.x = (uint32_t)__bfloat16_as_ushort(h0) | ((uint32_t)__bfloat16_as_ushort(h1) << 16);
    hv.y = (uint32_t)__bfloat16_as_ushort(h2) | ((uint32_t)__bfloat16_as_ushort(h3) << 16);
    lv.x = (uint32_t)__bfloat16_as_ushort(l0) | ((uint32_t)__bfloat16_as_ushort(l1) << 16);
    lv.y = (uint32_t)__bfloat16_as_ushort(l2) | ((uint32_t)__bfloat16_as_ushort(l3) << 16);
}

// ---------------- setup kernels (4 prelaunches) ----------------

__global__ void k_zero() {
    int i = blockIdx.x * 256 + threadIdx.x;
    if (i < BB * 32) { g_lossP[i] = 0.f; g_accP[i] = 0; }
}

__global__ void k_prep(const float* __restrict__ iW, const float* __restrict__ pW) {
    const int WN = LL * DD * DD;
    int i = blockIdx.x * 256 + threadIdx.x;
    if (i < WN) {
        __nv_bfloat16 h, l; split1(iW[i], h, l); g_iWh[i] = h; g_iWl[i] = l;
        split1(pW[i], h, l); g_pWh[i] = h; g_pWl[i] = l;
    }
    const size_t padTotal = (size_t)BB * (NWPAD - NWAY) * DD;
    const size_t stride = (size_t)gridDim.x * 256;
    __nv_bfloat16 z = __float2bfloat16(0.f);
    for (size_t idx = i; idx < padTotal; idx += stride) {
        size_t bb = idx / ((NWPAD - NWAY) * DD);
        size_t rem = idx % ((NWPAD - NWAY) * DD);
        size_t r = NWAY + rem / DD, d = rem % DD;
        g_Pah[(bb * NWPAD + r) * DD + d] = z;
        g_Pal[(bb * NWPAD + r) * DD + d] = z;
    }
}

__global__ void k_initV(const float* __restrict__ in) {
    __shared__ float red[8];
    int r = blockIdx.x;
    int b = r / NPAD, n = r % NPAD;
    int t = threadIdx.x;  // 128
    size_t po = ((size_t)b * NPAD + n) * DD;
    if (n >= NTOT) {
        ((uint2*)(g_Vh + po))[t] = make_uint2(0, 0);
        ((uint2*)(g_Vl + po))[t] = make_uint2(0, 0);
        return;
    }
    size_t ro = ((size_t)b * NTOT + n) * DD;
    float4 v = ((const float4*)(in + ro))[t];
    float ss = v.x*v.x + v.y*v.y + v.z*v.z + v.w*v.w;
    ss = blockSum(ss, red);
    float inv = 1.f / fmaxf(sqrtf(ss), 1e-12f);
    float4 o = make_float4(v.x*inv, v.y*inv, v.z*inv, v.w*inv);
    ((float4*)(g_V  + ro))[t] = o;
    ((float4*)(g_V0 + ro))[t] = o;
    uint2 hv, lv; split4(o, hv, lv);
    ((uint2*)(g_Vh + po))[t] = hv;
    ((uint2*)(g_Vl + po))[t] = lv;
}

__global__ void k_initP(const float* __restrict__ in) {
    __shared__ float red[8];
    size_t row = blockIdx.x;
    int t = threadIdx.x;
    float4 v = ((const float4*)(in + row * DD))[t];
    float ss = v.x*v.x + v.y*v.y + v.z*v.z + v.w*v.w;
    ss = blockSum(ss, red);
    float inv = 1.f / fmaxf(sqrtf(ss), 1e-12f);
    float4 o = make_float4(v.x*inv, v.y*inv, v.z*inv, v.w*inv);
    ((float4*)(g_P  + row * DD))[t] = o;
    ((float4*)(g_P0 + row * DD))[t] = o;
}

// ============== bf16 hi/lo split tensor-core NT GEMM (64x64, cp.async) ==============
#define GSTG 20480
__global__ __launch_bounds__(128) void k_gemm_bf(
    const __nv_bfloat16* __restrict__ Ah, const __nv_bfloat16* __restrict__ Al,
    const __nv_bfloat16* __restrict__ Bh, const __nv_bfloat16* __restrict__ Bl,
    float* __restrict__ C, int M, int N, int ldc,
    size_t strA, size_t strB, size_t strC)
{
    __shared__ __align__(16) uint8_t smem[2 * GSTG];

    int tid = threadIdx.x;
    int m0 = blockIdx.y * 64, n0 = blockIdx.x * 64;
    const __nv_bfloat16* pAh = Ah + (size_t)blockIdx.z * strA + (size_t)m0 * DD;
    const __nv_bfloat16* pAl = Al + (size_t)blockIdx.z * strA + (size_t)m0 * DD;
    const __nv_bfloat16* pBh = Bh + (size_t)blockIdx.z * strB + (size_t)n0 * DD;
    const __nv_bfloat16* pBl = Bl + (size_t)blockIdx.z * strB + (size_t)n0 * DD;
    float* Cb = C + (size_t)blockIdx.z * strC;

    int warp = tid >> 5, lane = tid & 31;
    int warpM = warp >> 1, warpN = warp & 1;
    int j = lane >> 3, r8 = lane & 7;

    uint32_t offA[2], offB[2];
    #pragma unroll
    for (int mt = 0; mt < 2; mt++) {
        int row = warpM * 32 + mt * 16 + (j & 1) * 8 + r8;
        offA[mt] = (uint32_t)(row * 80 + (j >> 1) * 16);
    }
    #pragma unroll
    for (int nt2 = 0; nt2 < 2; nt2++) {
        int n = warpN * 32 + nt2 * 16 + (j >> 1) * 8 + r8;
        offB[nt2] = (uint32_t)(n * 80 + (j & 1) * 16);
    }
    uint32_t sbase = smem_u32(smem);

    float acc[2][4][4];
    #pragma unroll
    for (int mt = 0; mt < 2; mt++)
        #pragma unroll
        for (int nt = 0; nt < 4; nt++)
            #pragma unroll
            for (int r = 0; r < 4; r++) acc[mt][nt][r] = 0.f;

    int r0s = tid >> 2, c0s = tid & 3;
    int r1s = (tid + 128) >> 2, c1s = (tid + 128) & 3;

    auto issue = [&](int st, int kg) {
        uint32_t sb = sbase + st * GSTG;
        cpasync16(sb +          r0s*80 + c0s*16, pAh + (size_t)r0s*DD + kg + c0s*8);
        cpasync16(sb +          r1s*80 + c1s*16, pAh + (size_t)r1s*DD + kg + c1s*8);
        cpasync16(sb + 5120  +  r0s*80 + c0s*16, pAl + (size_t)r0s*DD + kg + c0s*8);
        cpasync16(sb + 5120  +  r1s*80 + c1s*16, pAl + (size_t)r1s*DD + kg + c1s*8);
        cpasync16(sb + 10240 +  r0s*80 + c0s*16, pBh + (size_t)r0s*DD + kg + c0s*8);
        cpasync16(sb + 10240 +  r1s*80 + c1s*16, pBh + (size_t)r1s*DD + kg + c1s*8);
        cpasync16(sb + 15360 +  r0s*80 + c0s*16, pBl + (size_t)r0s*DD + kg + c0s*8);
        cpasync16(sb + 15360 +  r1s*80 + c1s*16, pBl + (size_t)r1s*DD + kg + c1s*8);
        cpcommit();
    };

    issue(0, 0);
    int buf = 0;
    const int iters = DD / 32;
    for (int it = 0; it < iters; it++) {
        cpwait0();
        __syncthreads();
        if (it + 1 < iters) issue(buf ^ 1, (it + 1) * 32);
        uint32_t sb = sbase + buf * GSTG;
        #pragma unroll
        for (int s = 0; s < 2; s++) {
            uint32_t so = s * 32;
            uint32_t ah[2][4], al[2][4], bh[4][2], bl[4][2];
            #pragma unroll
            for (int mt = 0; mt < 2; mt++) {
                ldsm4(ah[mt][0], ah[mt][1], ah[mt][2], ah[mt][3], sb + offA[mt] + so);
                ldsm4(al[mt][0], al[mt][1], al[mt][2], al[mt][3], sb + 5120 + offA[mt] + so);
            }
            #pragma unroll
            for (int nt2 = 0; nt2 < 2; nt2++) {
                uint32_t q0,q1,q2,q3;
                ldsm4(q0,q1,q2,q3, sb + 10240 + offB[nt2] + so);
                bh[nt2*2][0]=q0; bh[nt2*2][1]=q1; bh[nt2*2+1][0]=q2; bh[nt2*2+1][1]=q3;
                ldsm4(q0,q1,q2,q3, sb + 15360 + offB[nt2] + so);
                bl[nt2*2][0]=q0; bl[nt2*2][1]=q1; bl[nt2*2+1][0]=q2; bl[nt2*2+1][1]=q3;
            }
            #pragma unroll
            for (int mt = 0; mt < 2; mt++)
                #pragma unroll
                for (int nt = 0; nt < 4; nt++) {
                    mma16(acc[mt][nt], ah[mt], bh[nt]);
                    mma16(acc[mt][nt], ah[mt], bl[nt]);
                    mma16(acc[mt][nt], al[mt], bh[nt]);
                }
        }
        buf ^= 1;
    }

    #pragma unroll
    for (int mt = 0; mt < 2; mt++) {
        #pragma unroll
        for (int nt = 0; nt < 4; nt++) {
            int row = m0 + warpM * 32 + mt * 16 + (lane >> 2);
            int col = n0 + warpN * 32 + nt * 8 + (lane & 3) * 2;
            if (row < M) {
                if (col < N)     Cb[(size_t)row * ldc + col]     = acc[mt][nt][0];
                if (col + 1 < N) Cb[(size_t)row * ldc + col + 1] = acc[mt][nt][1];
            }
            if (row + 8 < M) {
                if (col < N)     Cb[(size_t)(row + 8) * ldc + col]     = acc[mt][nt][2];
                if (col + 1 < N) Cb[(size_t)(row + 8) * ldc + col + 1] = acc[mt][nt][3];
            }
        }
    }
}

// ============== dual W-GEMM: 64x128 tile; y<700 instance, y>=700 proto ==============
#define GW 30720
#define YT_INST 700   // 44800/64
#define YT_PROT 80    // 5120/64
__global__ __launch_bounds__(256) void k_gemm_w(
    const __nv_bfloat16* __restrict__ iAh, const __nv_bfloat16* __restrict__ iAl,
    const __nv_bfloat16* __restrict__ iBh, const __nv_bfloat16* __restrict__ iBl,
    float* __restrict__ iC,
    const __nv_bfloat16* __restrict__ qAh, const __nv_bfloat16* __restrict__ qAl,
    const __nv_bfloat16* __restrict__ qBh, const __nv_bfloat16* __restrict__ qBl,
    float* __restrict__ qC)
{
    extern __shared__ __align__(16) uint8_t dsm[];

    int tid = threadIdx.x;
    int yt = blockIdx.y;
    bool inst = yt < YT_INST;
    int m0 = (inst ? yt : (yt - YT_INST)) * 64;
    int n0 = blockIdx.x * 128;
    const __nv_bfloat16* pAh = (inst ? iAh : qAh) + (size_t)m0 * DD;
    const __nv_bfloat16* pAl = (inst ? iAl : qAl) + (size_t)m0 * DD;
    const __nv_bfloat16* pBh = (inst ? iBh : qBh) + (size_t)n0 * DD;
    const __nv_bfloat16* pBl = (inst ? iBl : qBl) + (size_t)n0 * DD;
    float* C = inst ? iC : qC;

    int warp = tid >> 5, lane = tid & 31;
    int warpM = warp >> 2, warpN = warp & 3;
    int j = lane >> 3, r8 = lane & 7;

    uint32_t offA[2], offB[2];
    #pragma unroll
    for (int mt = 0; mt < 2; mt++) {
        int row = warpM * 32 + mt * 16 + (j & 1) * 8 + r8;
        offA[mt] = (uint32_t)(row * 80 + (j >> 1) * 16);
    }
    #pragma unroll
    for (int nt2 = 0; nt2 < 2; nt2++) {
        int n = warpN * 32 + nt2 * 16 + (j >> 1) * 8 + r8;
        offB[nt2] = (uint32_t)(n * 80 + (j & 1) * 16);
    }
    uint32_t sbase = smem_u32(dsm);

    float acc[2][4][4];
    #pragma unroll
    for (int mt = 0; mt < 2; mt++)
        #pragma unroll
        for (int nt = 0; nt < 4; nt++)
            #pragma unroll
            for (int r = 0; r < 4; r++) acc[mt][nt][r] = 0.f;

    int rA = tid >> 2, cA = tid & 3;
    int rB1 = (tid + 256) >> 2, cB1 = (tid + 256) & 3;

    auto issue = [&](int st, int kg) {
        uint32_t sb = sbase + st * GW;
        cpasync16(sb +          rA*80 + cA*16,  pAh + (size_t)rA*DD + kg + cA*8);
        cpasync16(sb + 5120  +  rA*80 + cA*16,  pAl + (size_t)rA*DD + kg + cA*8);
        cpasync16(sb + 10240 +  rA*80 + cA*16,  pBh + (size_t)rA*DD + kg + cA*8);
        cpasync16(sb + 10240 +  rB1*80 + cB1*16, pBh + (size_t)rB1*DD + kg + cB1*8);
        cpasync16(sb + 20480 +  rA*80 + cA*16,  pBl + (size_t)rA*DD + kg + cA*8);
        cpasync16(sb + 20480 +  rB1*80 + cB1*16, pBl + (size_t)rB1*DD + kg + cB1*8);
        cpcommit();
    };

    issue(0, 0);
    int buf = 0;
    const int iters = DD / 32;
    for (int it = 0; it < iters; it++) {
        cpwait0();
        __syncthreads();
        if (it + 1 < iters) issue(buf ^ 1, (it + 1) * 32);
        uint32_t sb = sbase + buf * GW;
        #pragma unroll
        for (int s = 0; s < 2; s++) {
            uint32_t so = s * 32;
            uint32_t ah[2][4], al[2][4], bh[4][2], bl[4][2];
            #pragma unroll
            for (int mt = 0; mt < 2; mt++) {
                ldsm4(ah[mt][0], ah[mt][1], ah[mt][2], ah[mt][3], sb + offA[mt] + so);
                ldsm4(al[mt][0], al[mt][1], al[mt][2], al[mt][3], sb + 5120 + offA[mt] + so);
            }
            #pragma unroll
            for (int nt2 = 0; nt2 < 2; nt2++) {
                uint32_t q0,q1,q2,q3;
                ldsm4(q0,q1,q2,q3, sb + 10240 + offB[nt2] + so);
                bh[nt2*2][0]=q0; bh[nt2*2][1]=q1; bh[nt2*2+1][0]=q2; bh[nt2*2+1][1]=q3;
                ldsm4(q0,q1,q2,q3, sb + 20480 + offB[nt2] + so);
                bl[nt2*2][0]=q0; bl[nt2*2][1]=q1; bl[nt2*2+1][0]=q2; bl[nt2*2+1][1]=q3;
            }
            #pragma unroll
            for (int mt = 0; mt < 2; mt++)
                #pragma unroll
                for (int nt = 0; nt < 4; nt++) {
                    mma16(acc[mt][nt], ah[mt], bh[nt]);
                    mma16(acc[mt][nt], ah[mt], bl[nt]);
                    mma16(acc[mt][nt], al[mt], bh[nt]);
                }
        }
        buf ^= 1;
    }

    #pragma unroll
    for (int mt = 0; mt < 2; mt++) {
        #pragma unroll
        for (int nt = 0; nt < 4; nt++) {
            int row = m0 + warpM * 32 + mt * 16 + (lane >> 2);
            int col = n0 + warpN * 32 + nt * 8 + (lane & 3) * 2;
            C[(size_t)row * DD + col]           = acc[mt][nt][0];
            C[(size_t)row * DD + col + 1]       = acc[mt][nt][1];
            C[(size_t)(row + 8) * DD + col]     = acc[mt][nt][2];
            C[(size_t)(row + 8) * DD + col + 1] = acc[mt][nt][3];
        }
    }
}

// ============== symmetric sim GEMM: lower-triangle tiles + mirror write ==============
__constant__ int c_ty[6] = {0, 1, 1, 2, 2, 2};
__constant__ int c_tx[6] = {0, 0, 1, 0, 1, 2};
__global__ __launch_bounds__(128) void k_gemm_sym(
    const __nv_bfloat16* __restrict__ Vh, const __nv_bfloat16* __restrict__ Vl,
    float* __restrict__ C)
{
    __shared__ __align__(16) uint8_t smem[2 * GSTG];

    int tid = threadIdx.x;
    int ty = c_ty[blockIdx.x], tx = c_tx[blockIdx.x];
    int m0 = ty * 64, n0 = tx * 64;
    const __nv_bfloat16* pAh = Vh + (size_t)blockIdx.z * NPAD * DD + (size_t)m0 * DD;
    const __nv_bfloat16* pAl = Vl + (size_t)blockIdx.z * NPAD * DD + (size_t)m0 * DD;
    const __nv_bfloat16* pBh = Vh + (size_t)blockIdx.z * NPAD * DD + (size_t)n0 * DD;
    const __nv_bfloat16* pBl = Vl + (size_t)blockIdx.z * NPAD * DD + (size_t)n0 * DD;
    float* Cb = C + (size_t)blockIdx.z * NTOT * NTOT;

    int warp = tid >> 5, lane = tid & 31;
    int warpM = warp >> 1, warpN = warp & 1;
    int j = lane >> 3, r8 = lane & 7;

    uint32_t offA[2], offB[2];
    #pragma unroll
    for (int mt = 0; mt < 2; mt++) {
        int row = warpM * 32 + mt * 16 + (j & 1) * 8 + r8;
        offA[mt] = (uint32_t)(row * 80 + (j >> 1) * 16);
    }
    #pragma unroll
    for (int nt2 = 0; nt2 < 2; nt2++) {
        int n = warpN * 32 + nt2 * 16 + (j >> 1) * 8 + r8;
        offB[nt2] = (uint32_t)(n * 80 + (j & 1) * 16);
    }
    uint32_t sbase = smem_u32(smem);

    float acc[2][4][4];
    #pragma unroll
    for (int mt = 0; mt < 2; mt++)
        #pragma unroll
        for (int nt = 0; nt < 4; nt++)
            #pragma unroll
            for (int r = 0; r < 4; r++) acc[mt][nt][r] = 0.f;

    int r0s = tid >> 2, c0s = tid & 3;
    int r1s = (tid + 128) >> 2, c1s = (tid + 128) & 3;

    auto issue = [&](int st, int kg) {
        uint32_t sb = sbase + st * GSTG;
        cpasync16(sb +          r0s*80 + c0s*16, pAh + (size_t)r0s*DD + kg + c0s*8);
        cpasync16(sb +          r1s*80 + c1s*16, pAh + (size_t)r1s*DD + kg + c1s*8);
        cpasync16(sb + 5120  +  r0s*80 + c0s*16, pAl + (size_t)r0s*DD + kg + c0s*8);
        cpasync16(sb + 5120  +  r1s*80 + c1s*16, pAl + (size_t)r1s*DD + kg + c1s*8);
        cpasync16(sb + 10240 +  r0s*80 + c0s*16, pBh + (size_t)r0s*DD + kg + c0s*8);
        cpasync16(sb + 10240 +  r1s*80 + c1s*16, pBh + (size_t)r1s*DD + kg + c1s*8);
        cpasync16(sb + 15360 +  r0s*80 + c0s*16, pBl + (size_t)r0s*DD + kg + c0s*8);
        cpasync16(sb + 15360 +  r1s*80 + c1s*16, pBl + (size_t)r1s*DD + kg + c1s*8);
        cpcommit();
    };

    issue(0, 0);
    int buf = 0;
    const int iters = DD / 32;
    for (int it = 0; it < iters; it++) {
        cpwait0();
        __syncthreads();
        if (it + 1 < iters) issue(buf ^ 1, (it + 1) * 32);
        uint32_t sb = sbase + buf * GSTG;
        #pragma unroll
        for (int s = 0; s < 2; s++) {
            uint32_t so = s * 32;
            uint32_t ah[2][4], al[2][4], bh[4][2], bl[4][2];
            #pragma unroll
            for (int mt = 0; mt < 2; mt++) {
                ldsm4(ah[mt][0], ah[mt][1], ah[mt][2], ah[mt][3], sb + offA[mt] + so);
                ldsm4(al[mt][0], al[mt][1], al[mt][2], al[mt][3], sb + 5120 + offA[mt] + so);
            }
            #pragma unroll
            for (int nt2 = 0; nt2 < 2; nt2++) {
                uint32_t q0,q1,q2,q3;
                ldsm4(q0,q1,q2,q3, sb + 10240 + offB[nt2] + so);
                bh[nt2*2][0]=q0; bh[nt2*2][1]=q1; bh[nt2*2+1][0]=q2; bh[nt2*2+1][1]=q3;
                ldsm4(q0,q1,q2,q3, sb + 15360 + offB[nt2] + so);
                bl[nt2*2][0]=q0; bl[nt2*2][1]=q1; bl[nt2*2+1][0]=q2; bl[nt2*2+1][1]=q3;
            }
            #pragma unroll
            for (int mt = 0; mt < 2; mt++)
                #pragma unroll
                for (int nt = 0; nt < 4; nt++) {
                    mma16(acc[mt][nt], ah[mt], bh[nt]);
                    mma16(acc[mt][nt], ah[mt], bl[nt]);
                    mma16(acc[mt][nt], al[mt], bh[nt]);
                }
        }
        buf ^= 1;
    }

    #pragma unroll
    for (int mt = 0; mt < 2; mt++) {
        #pragma unroll
        for (int nt = 0; nt < 4; nt++) {
            int row = m0 + warpM * 32 + mt * 16 + (lane >> 2);
            int col = n0 + warpN * 32 + nt * 8 + (lane & 3) * 2;
            if (row < NTOT) {
                if (col < NTOT)     Cb[(size_t)row * NTOT + col]     = acc[mt][nt][0];
                if (col + 1 < NTOT) Cb[(size_t)row * NTOT + col + 1] = acc[mt][nt][1];
            }
            if (row + 8 < NTOT) {
                if (col < NTOT)     Cb[(size_t)(row + 8) * NTOT + col]     = acc[mt][nt][2];
                if (col + 1 < NTOT) Cb[(size_t)(row + 8) * NTOT + col + 1] = acc[mt][nt][3];
            }
        }
    }

    if (ty != tx) {
        __syncthreads();
        float* sT = (float*)smem;   // 64x65 floats
        #pragma unroll
        for (int mt = 0; mt < 2; mt++) {
            #pragma unroll
            for (int nt = 0; nt < 4; nt++) {
                int rl = warpM * 32 + mt * 16 + (lane >> 2);
                int cl = warpN * 32 + nt * 8 + (lane & 3) * 2;
                sT[(cl)     * 65 + rl]     = acc[mt][nt][0];
                sT[(cl + 1) * 65 + rl]     = acc[mt][nt][1];
                sT[(cl)     * 65 + rl + 8] = acc[mt][nt][2];
                sT[(cl + 1) * 65 + rl + 8] = acc[mt][nt][3];
            }
        }
        __syncthreads();
        for (int idx = tid; idx < 64 * 64; idx += 128) {
            int r = idx >> 6, c = idx & 63;
            int grow = n0 + r, gcol = m0 + c;
            if (grow < NTOT && gcol < NTOT)
                Cb[(size_t)grow * NTOT + gcol] = sT[r * 65 + c];
        }
    }
}

// ============== warp-per-row sparse step: top-5 + softmax + gather, no smem ==============
__global__ __launch_bounds__(256) void k_sparse(
    const float* __restrict__ sim, const float* __restrict__ V,
    __nv_bfloat16* __restrict__ mh, __nv_bfloat16* __restrict__ ml)
{
    int tid = threadIdx.x, w = tid >> 5, lane = tid & 31;
    int row = blockIdx.x * 8 + w;
    int b = row / NTOT;
    const float* sr = sim + (size_t)row * NTOT;
    float v[6];
    #pragma unroll
    for (int jj = 0; jj < 6; jj++) {
        int c = lane + jj * 32;
        v[jj] = (c < NTOT) ? sr[c] : -INFINITY;
    }
    float cv[KNEI]; int ci[KNEI];
    #pragma unroll
    for (int p = 0; p < KNEI; p++) {
        float bv = -INFINITY; int bc = 0x7fffffff;
        #pragma unroll
        for (int jj = 0; jj < 6; jj++)
            if (v[jj] > bv) { bv = v[jj]; bc = lane + jj * 32; }
        #pragma unroll
        for (int off = 16; off; off >>= 1) {
            float ov = __shfl_down_sync(0xffffffffu, bv, off);
            int   oc = __shfl_down_sync(0xffffffffu, bc, off);
            if (ov > bv || (ov == bv && oc < bc)) { bv = ov; bc = oc; }
        }
        bv = __shfl_sync(0xffffffffu, bv, 0);
        bc = __shfl_sync(0xffffffffu, bc, 0);
        cv[p] = bv; ci[p] = bc;
        if ((bc & 31) == lane) v[bc >> 5] = -INFINITY;
    }
    float wj[KNEI];
    {
        float mx = cv[0], s = 0.f;
        #pragma unroll
        for (int p = 0; p < KNEI; p++) { wj[p] = expf((cv[p] - mx) * TAUINV); s += wj[p]; }
        float inv = 1.f / s;
        #pragma unroll
        for (int p = 0; p < KNEI; p++) wj[p] *= inv;
    }
    const float* base = V + (size_t)b * NTOT * DD;
    const float4* nb[KNEI];
    #pragma unroll
    for (int p = 0; p < KNEI; p++) nb[p] = (const float4*)(base + (size_t)ci[p] * DD);
    float4 acc[4];
    #pragma unroll
    for (int i = 0; i < 4; i++) acc[i] = make_float4(0,0,0,0);
    #pragma unroll
    for (int p = 0; p < KNEI; p++) {
        #pragma unroll
        for (int i = 0; i < 4; i++) {
            float4 x = nb[p][lane + 32 * i];
            acc[i].x += wj[p]*x.x; acc[i].y += wj[p]*x.y;
            acc[i].z += wj[p]*x.z; acc[i].w += wj[p]*x.w;
        }
    }
    uint2* mhr = (uint2*)(mh + (size_t)row * DD);
    uint2* mlr = (uint2*)(ml + (size_t)row * DD);
    #pragma unroll
    for (int i = 0; i < 4; i++) {
        uint2 hv, lv; split4(acc[i], hv, lv);
        mhr[lane + 32 * i] = hv;
        mlr[lane + 32 * i] = lv;
    }
}

// fused prototype branch: sims + top-5 softmax + gather -> PMsg hi/lo
__global__ __launch_bounds__(256) void k_proto(const float* __restrict__ P,
                                               __nv_bfloat16* __restrict__ mh,
                                               __nv_bfloat16* __restrict__ ml)
{
    __shared__ float sP[NWAY * DD];
    __shared__ float sSim[NWAY][NWAY];
    __shared__ float sW[NWAY][KNEI];
    __shared__ int   sI[NWAY][KNEI];
    int b = blockIdx.x, tid = threadIdx.x;
    const float* Pb = P + (size_t)b * NWAY * DD;
    for (int i = tid; i < NWAY * DD; i += 256) sP[i] = Pb[i];
    __syncthreads();
    int warp = tid >> 5, lane = tid & 31;
    for (int p = warp; p < NWAY * NWAY; p += 8) {
        int r = p / NWAY, c = p % NWAY;
        float d = 0.f;
        for (int i = lane; i < DD; i += 32) d += sP[r * DD + i] * sP[c * DD + i];
        d = warpSum(d);
        if (lane == 0) sSim[r][c] = d;
    }
    __syncthreads();
    if (tid < NWAY) {
        float v[NWAY];
        #pragma unroll
        for (int c = 0; c < NWAY; c++) v[c] = sSim[tid][c];
        float cv[KNEI]; int ci[KNEI];
        #pragma unroll
        for (int p = 0; p < KNEI; p++) {
            float bv = -INFINITY; int bc = 0;
            #pragma unroll
            for (int c = 0; c < NWAY; c++)
                if (v[c] > bv) { bv = v[c]; bc = c; }
            cv[p] = bv; ci[p] = bc; v[bc] = -INFINITY;
        }
        float mx = cv[0], e[KNEI], s = 0.f;
        #pragma unroll
        for (int p = 0; p < KNEI; p++) { e[p] = expf((cv[p] - mx) * TAUINV); s += e[p]; }
        float inv = 1.f / s;
        #pragma unroll
        for (int p = 0; p < KNEI; p++) { sW[tid][p] = e[p] * inv; sI[tid][p] = ci[p]; }
    }
    __syncthreads();
    size_t base = (size_t)b * NWAY * DD;
    for (int e = tid; e < NWAY * DD; e += 256) {
        int r = e >> 9, d = e & (DD - 1);
        float a = 0.f;
        #pragma unroll
        for (int p = 0; p < KNEI; p++) a += sW[r][p] * sP[sI[r][p] * DD + d];
        __nv_bfloat16 hh, llv; split1(a, hh, llv);
        mh[base + e] = hh; ml[base + e] = llv;
    }
}

// ============== merged epilogue: rows [0, BB*NTOT) = V path, rest = P path ==============
__global__ void k_epi(
    float* __restrict__ V, const float* __restrict__ V0, const float* __restrict__ Gv,
    const float* __restrict__ iBias, const float* __restrict__ iScale,
    float* __restrict__ P, const float* __restrict__ P0, const float* __restrict__ Gp,
    const float* __restrict__ pBias, const float* __restrict__ pScale,
    int layer, __nv_bfloat16* __restrict__ Vh, __nv_bfloat16* __restrict__ Vl)
{
    __shared__ float red[8];
    int rowg = blockIdx.x;
    int t = threadIdx.x;  // 128
    bool isV = rowg < BB * NTOT;
    int row = isV ? rowg : (rowg - BB * NTOT);
    float s = isV ? iScale[layer] : pScale[layer];
    float*       X  = isV ? V  : P;
    const float* X0 = isV ? V0 : P0;
    const float* G  = isV ? Gv : Gp;
    const float* bias = isV ? iBias : pBias;
    float4 vv = ((const float4*)(X  + (size_t)row * DD))[t];
    float4 gg = ((const float4*)(G  + (size_t)row * DD))[t];
    float4 bb = ((const float4*)(bias))[t];
    float4 v0 = ((const float4*)(X0 + (size_t)row * DD))[t];
    float4 r4;
    r4.x = 0.8f*(vv.x + s*tanhf(gg.x + bb.x)) + 0.2f*v0.x;
    r4.y = 0.8f*(vv.y + s*tanhf(gg.y + bb.y)) + 0.2f*v0.y;
    r4.z = 0.8f*(vv.z + s*tanhf(gg.z + bb.z)) + 0.2f*v0.z;
    r4.w = 0.8f*(vv.w + s*tanhf(gg.w + bb.w)) + 0.2f*v0.w;
    float ss = r4.x*r4.x + r4.y*r4.y + r4.z*r4.z + r4.w*r4.w;
    ss = blockSum(ss, red);
    float inv = 1.f / fmaxf(sqrtf(ss), 1e-12f);
    r4.x*=inv; r4.y*=inv; r4.z*=inv; r4.w*=inv;
    ((float4*)(X + (size_t)row * DD))[t] = r4;
    if (isV) {
        int b = row / NTOT, n = row % NTOT;
        size_t po = ((size_t)b * NPAD + n) * DD;
        uint2 hv, lv; split4(r4, hv, lv);
        ((uint2*)(Vh + po))[t] = hv;
        ((uint2*)(Vl + po))[t] = lv;
    }
}

// ============== fused VC + Pa + Gram (one block per batch) ==============
__global__ __launch_bounds__(256) void k_vcg(
    const float* __restrict__ V, const float* __restrict__ P,
    float* __restrict__ Pa, __nv_bfloat16* __restrict__ Pah,
    __nv_bfloat16* __restrict__ Pal, float* __restrict__ G,
    const float* __restrict__ alphaPtr)
{
    __shared__ float sPa[NWAY * DD];
    int b = blockIdx.x;
    int tid = threadIdx.x, w = tid >> 5, lane = tid & 31;
    float a = *alphaPtr;
    for (int c = w; c < NWAY; c += 8) {
        const float* base = V + ((size_t)b * NTOT + (size_t)c * KSHOT) * DD;
        float acc[16];
        #pragma unroll
        for (int i = 0; i < 16; i++) acc[i] = 0.f;
        #pragma unroll
        for (int k = 0; k < KSHOT; k++)
            #pragma unroll
            for (int i = 0; i < 16; i++)
                acc[i] += base[(size_t)k * DD + lane + 32 * i];
        float ss = 0.f;
        #pragma unroll
        for (int i = 0; i < 16; i++) { acc[i] *= 0.2f; ss += acc[i] * acc[i]; }
        ss = warpSum(ss);
        float inv = 1.f / fmaxf(sqrtf(ss), 1e-12f);
        const float* Prow = P + ((size_t)b * NWAY + c) * DD;
        float pa[16]; float ss2 = 0.f;
        #pragma unroll
        for (int i = 0; i < 16; i++) {
            pa[i] = a * Prow[lane + 32 * i] + (1.f - a) * acc[i] * inv;
            ss2 += pa[i] * pa[i];
        }
        ss2 = warpSum(ss2);
        float inv2 = 1.f / fmaxf(sqrtf(ss2), 1e-12f);
        float* PaRow = Pa + ((size_t)b * NWAY + c) * DD;
        __nv_bfloat16* hRow = Pah + ((size_t)b * NWPAD + c) * DD;
        __nv_bfloat16* lRow = Pal + ((size_t)b * NWPAD + c) * DD;
        #pragma unroll
        for (int i = 0; i < 16; i++) {
            float v = pa[i] * inv2;
            int d = lane + 32 * i;
            PaRow[d] = v;
            sPa[c * DD + d] = v;
            __nv_bfloat16 hh, ll; split1(v, hh, ll);
            hRow[d] = hh; lRow[d] = ll;
        }
    }
    __syncthreads();
    for (int p = w; p < NWAY * NWAY; p += 8) {
        int i = p / NWAY, jc = p % NWAY;
        float d = 0.f;
        for (int k = lane; k < DD; k += 32) d += sPa[i * DD + k] * sPa[jc * DD + k];
        d = warpSum(d);
        if (lane == 0) G[(size_t)b * NWAY * NWAY + p] = d;
    }
}

// warp-per-row guidance
__global__ __launch_bounds__(256) void k_guide2(
    float* __restrict__ V, __nv_bfloat16* __restrict__ Vh, __nv_bfloat16* __restrict__ Vl,
    const float* __restrict__ Pa, const float* __restrict__ G,
    const float* __restrict__ simsQ, const float* __restrict__ betaPtr,
    const int* __restrict__ qy, int layer, int writeV)
{
    __shared__ float sPa[NWAY * DD];
    __shared__ float sG[NWAY * NWAY];
    __shared__ float sSoft[8][NWAY];
    int b = blockIdx.x;
    int tid = threadIdx.x, w = tid >> 5, lane = tid & 31;
    float beta = *betaPtr;
    if (writeV) {
        const float* PaB = Pa + (size_t)b * NWAY * DD;
        for (int i = tid; i < NWAY * DD; i += 256) sPa[i] = PaB[i];
    }
    for (int i = tid; i < NWAY * NWAY; i += 256) sG[i] = G[(size_t)b * NWAY * NWAY + i];
    __syncthreads();
    int gw = blockIdx.y * 8 + w;
    float localLoss = 0.f; int localAcc = 0;
    for (int r = gw; r < NTOT; r += 32) {
        if (!writeV && r < NKQ) continue;
        float s = (lane < NWAY) ? simsQ[((size_t)b * NPAD + r) * NWPAD + lane] : -INFINITY;
        float mx = s;
        #pragma unroll
        for (int off = 16; off; off >>= 1) mx = fmaxf(mx, __shfl_xor_sync(0xffffffffu, mx, off));
        float e = (lane < NWAY) ? expf((s - mx) * TAUINV) : 0.f;
        float sum = warpSum(e);
        float soft = e / sum;
        if (lane < NWAY) sSoft[w][lane] = soft;
        __syncwarp();
        float tj = 0.f;
        if (lane < NWAY) {
            #pragma unroll
            for (int m = 0; m < NWAY; m++) tj += sSoft[w][m] * sG[m * NWAY + lane];
        }
        float ob = 1.f - beta;
        float contrib = (lane < NWAY) ? soft * (2.f * beta * ob * s + ob * ob * tj) : 0.f;
        float n2 = beta * beta + warpSum(contrib);
        float invn = 1.f / fmaxf(sqrtf(n2), 1e-12f);
        if (writeV) {
            float* Vrow = V + ((size_t)b * NTOT + r) * DD;
            __nv_bfloat16* VhRow = Vh + ((size_t)b * NPAD + r) * DD;
            __nv_bfloat16* VlRow = Vl + ((size_t)b * NPAD + r) * DD;
            #pragma unroll
            for (int i = 0; i < 16; i++) {
                int d = lane + 32 * i;
                float g = 0.f;
                #pragma unroll
                for (int m = 0; m < NWAY; m++) g += sSoft[w][m] * sPa[m * DD + d];
                float nv = (beta * Vrow[d] + ob * g) * invn;
                Vrow[d] = nv;
                __nv_bfloat16 hh, ll; split1(nv, hh, ll);
                VhRow[d] = hh; VlRow[d] = ll;
            }
        }
        if (r >= NKQ) {
            float logit = (lane < NWAY) ? 5.f * invn * (beta * s + ob * tj) : -INFINITY;
            float m2 = logit;
            #pragma unroll
            for (int off = 16; off; off >>= 1) m2 = fmaxf(m2, __shfl_xor_sync(0xffffffffu, m2, off));
            float ee = (lane < NWAY) ? expf(logit - m2) : 0.f;
            float ssum = warpSum(ee);
            float lse = m2 + logf(ssum);
            int lbl = qy[b * QN + (r - NKQ)];
            float ll = __shfl_sync(0xffffffffu, logit, lbl);
            if (lane == 0) localLoss += lse - ll;
            if (layer == LL - 1) {
                float bv = logit; int bi = lane;
                #pragma unroll
                for (int off = 16; off; off >>= 1) {
                    float ov = __shfl_xor_sync(0xffffffffu, bv, off);
                    int   oi = __shfl_xor_sync(0xffffffffu, bi, off);
                    if (ov > bv || (ov == bv && oi < bi)) { bv = ov; bi = oi; }
                }
                if (lane == 0) localAcc += (bi == lbl) ? 1 : 0;
            }
        }
    }
    if (lane == 0) {
        int pi = b * 32 + gw;
        g_lossP[pi] += localLoss;
        if (layer == LL - 1) g_accP[pi] = localAcc;
    }
}

__global__ void k_final(float* __restrict__ out) {
    __shared__ float red[8];
    int t = threadIdx.x;
    float ls = 0.f, ac = 0.f;
    for (int i = t; i < BB * 32; i += 256) { ls += g_lossP[i]; ac += (float)g_accP[i]; }
    float L = blockSum(ls, red);
    float A = blockSum(ac, red);
    if (t == 0) {
        out[0] = L / (float)(BB * QN * LL);
        out[1] = A / (float)(BB * QN);
    }
}

// ---------------- launch ----------------
extern "C" void kernel_launch(void* const* d_in, const int* in_sizes, int n_in,
                              void* d_out, int out_size)
{
    const float* V_feat = (const float*)d_in[0];
    const float* P_feat = (const float*)d_in[1];
    const int*   qy     = (const int*)  d_in[2];
    const float* igbW   = (const float*)d_in[3];
    const float* igbB   = (const float*)d_in[4];
    const float* igbS   = (const float*)d_in[5];
    const float* pgbW   = (const float*)d_in[6];
    const float* pgbB   = (const float*)d_in[7];
    const float* pgbS   = (const float*)d_in[8];
    const float* alpha  = (const float*)d_in[9];
    const float* beta   = (const float*)d_in[10];
    float* out = (float*)d_out;

    float *pV, *pV0, *pGemm, *pP, *pP0, *pPgemm, *pPa, *pSim, *pSimQ, *pG;
    __nv_bfloat16 *pVh, *pVl, *pMh, *pMl, *pPMh, *pPMl, *pPah, *pPal, *piWh, *piWl, *ppWh, *ppWl;
    cudaGetSymbolAddress((void**)&pV,    g_V);
    cudaGetSymbolAddress((void**)&pV0,   g_V0);
    cudaGetSymbolAddress((void**)&pVh,   g_Vh);
    cudaGetSymbolAddress((void**)&pVl,   g_Vl);
    cudaGetSymbolAddress((void**)&pMh,   g_Mh);
    cudaGetSymbolAddress((void**)&pMl,   g_Ml);
    cudaGetSymbolAddress((void**)&pGemm, g_gemm);
    cudaGetSymbolAddress((void**)&pP,    g_P);
    cudaGetSymbolAddress((void**)&pP0,   g_P0);
    cudaGetSymbolAddress((void**)&pPMh,  g_PMh);
    cudaGetSymbolAddress((void**)&pPMl,  g_PMl);
    cudaGetSymbolAddress((void**)&pPgemm,g_Pgemm);
    cudaGetSymbolAddress((void**)&pPa,   g_Pa);
    cudaGetSymbolAddress((void**)&pPah,  g_Pah);
    cudaGetSymbolAddress((void**)&pPal,  g_Pal);
    cudaGetSymbolAddress((void**)&pSim,  g_sim);
    cudaGetSymbolAddress((void**)&pSimQ, g_simQ);
    cudaGetSymbolAddress((void**)&pG,    g_G);
    cudaGetSymbolAddress((void**)&piWh,  g_iWh);
    cudaGetSymbolAddress((void**)&piWl,  g_iWl);
    cudaGetSymbolAddress((void**)&ppWh,  g_pWh);
    cudaGetSymbolAddress((void**)&ppWl,  g_pWl);

    cudaFuncSetAttribute(k_gemm_w, cudaFuncAttributeMaxDynamicSharedMemorySize, 2 * GW);

    k_zero<<<(BB * 32 + 255) / 256, 256>>>();
    k_prep<<<(LL * DD * DD + 255) / 256, 256>>>(igbW, pgbW);
    k_initV<<<BB * NPAD, 128>>>(V_feat);
    k_initP<<<BB * NWAY, 128>>>(P_feat);

    for (int i = 0; i < LL; i++) {
        // ---- graph step: sim + sparse + proto msg ----
        k_gemm_sym<<<dim3(6, 1, BB), 128>>>(pVh, pVl, pSim);
        k_sparse<<<(BB * NTOT) / 8, 256>>>(pSim, pV, pMh, pMl);
        k_proto<<<BB, 256>>>(pP, pPMh, pPMl);
        // ---- dual W-GEMM (64x128 tiles): instance + proto in one grid ----
        k_gemm_w<<<dim3(4, YT_INST + YT_PROT), 256, 2 * GW>>>(
            pMh, pMl, piWh + (size_t)i * DD * DD, piWl + (size_t)i * DD * DD, pGemm,
            pPMh, pPMl, ppWh + (size_t)i * DD * DD, ppWl + (size_t)i * DD * DD, pPgemm);
        // ---- merged epilogue (V rows then P rows) ----
        k_epi<<<BB * NTOT + BB * NWAY, 128>>>(
            pV, pV0, pGemm, igbB + (size_t)i * DD, igbS,
            pP, pP0, pPgemm, pgbB + (size_t)i * DD, pgbS,
            i, pVh, pVl);
        // ---- centers + adapted prototypes + Gram, simQ, guidance ----
        k_vcg<<<BB, 256>>>(pV, pP, pPa, pPah, pPal, pG, alpha);
        k_gemm_bf<<<dim3(1, 3, BB), 128>>>(pVh, pVl, pPah, pPal, pSimQ,
            NPAD, NWPAD, NWPAD, (size_t)NPAD * DD, (size_t)NWPAD * DD, (size_t)NPAD * NWPAD);
        int writeV = (i < LL - 1) ? 1 : 0;
        k_guide2<<<dim3(BB, 4), 256>>>(pV, pVh, pVl, pPa, pG, pSimQ, beta, qy, i, writeV);
    }
    k_final<<<1, 256>>>(out);
}